// round 5
// baseline (speedup 1.0000x reference)
#include <cuda_runtime.h>
#include <math.h>

// Problem constants
#define NU 50000
#define NI 50000
#define NN 100000          // NU + NI
#define DD 64
#define NNZ 3200000
#define NLAYERS 3
#define NB 4096
#define L2_REG 1e-5f

#define SCAN_CHUNK 1024
#define SCAN_NBLK ((NN + SCAN_CHUNK - 1) / SCAN_CHUNK)   // 98
#define STAT_READY (1 << 30)

// ---------------- device scratch (no allocs allowed) ----------------
__device__ __align__(256) float g_E0[NN * DD];
__device__ __align__(256) float g_E1[NN * DD];
__device__ __align__(256) float g_Lmul[NN * DD];
__device__ __align__(256) float g_alle[NN * DD * (NLAYERS + 1)];   // [N, 256]
__device__ int   g_deg[NN];          // zero-init; re-zeroed by k_scan each call
__device__ int   g_rowptr[NN + 1];
__device__ int   g_cursor[NN];
__device__ __align__(16) int2 g_edge[NNZ];   // (col, val bits)
__device__ int   g_stat[SCAN_NBLK];  // zero-init; reset by k_scatter each call
__device__ float g_acc[4];           // bpr_sum, sum u^2, sum p^2, sum n^2

// ---------------- f32x2 helpers (FFMA2: PTX-only pattern) ----------------
typedef unsigned long long ull;

__device__ __forceinline__ ull fma2(ull a, ull b, ull c) {
    ull d;
    asm("fma.rn.f32x2 %0, %1, %2, %3;" : "=l"(d) : "l"(a), "l"(b), "l"(c));
    return d;
}
__device__ __forceinline__ ull pk2(float lo, float hi) {
    ull d;
    asm("mov.b64 %0, {%1, %2};" : "=l"(d) : "f"(lo), "f"(hi));
    return d;
}
__device__ __forceinline__ float2 upk(ull v) {
    float2 f;
    asm("mov.b64 {%0, %1}, %2;" : "=f"(f.x), "=f"(f.y) : "l"(v));
    return f;
}

// ---------------- 1: count + E init + acc zero ----------------
__global__ void k_count_init(const int* __restrict__ rows,
                             const float* __restrict__ ue,
                             const float* __restrict__ ie) {
    int i = blockIdx.x * blockDim.x + threadIdx.x;
    if (i < NNZ) atomicAdd(&g_deg[rows[i]], 1);
    if (i < NN * (DD / 4)) {
        int n = i >> 4;
        int c = i & 15;
        const float4* src;
        int srow;
        if (n < NU) { src = (const float4*)ue; srow = n; }
        else        { src = (const float4*)ie; srow = n - NU; }
        float4 v = src[srow * 16 + c];
        ((float4*)g_E0)[i] = v;
        ((float4*)g_alle)[n * 64 + c] = v;
    }
    if (i < 4) g_acc[i] = 0.0f;
}

// ---------------- 2: single-pass scan (all 98 blocks co-resident) ----------------
__global__ void k_scan(void) {
    __shared__ int s[SCAN_CHUNK];
    __shared__ int wsum[4];
    __shared__ int s_off;
    int b = blockIdx.x;
    int t = threadIdx.x;
    int i = b * SCAN_CHUNK + t;
    int v = (i < NN) ? g_deg[i] : 0;
    if (i < NN) g_deg[i] = 0;            // maintain zero invariant for next call
    s[t] = v;
    __syncthreads();
    for (int off = 1; off < SCAN_CHUNK; off <<= 1) {
        int x = 0;
        if (t >= off) x = s[t - off];
        __syncthreads();
        s[t] += x;
        __syncthreads();
    }
    // publish aggregate
    if (t == SCAN_CHUNK - 1) atomicExch(&g_stat[b], s[t] | STAT_READY);
    // gather predecessor aggregates (all blocks resident: safe spin)
    int part = 0;
    if (t < b) {
        int st;
        do { st = atomicAdd(&g_stat[t], 0); } while (!(st & STAT_READY));
        part = st & (STAT_READY - 1);
    }
    #pragma unroll
    for (int off = 16; off > 0; off >>= 1)
        part += __shfl_xor_sync(0xffffffffu, part, off);
    if ((t & 31) == 0 && (t >> 5) < 4) wsum[t >> 5] = part;   // b <= 97 < 128
    __syncthreads();
    if (t == 0) s_off = wsum[0] + wsum[1] + wsum[2] + wsum[3];
    __syncthreads();
    int off = s_off;
    if (i < NN) {
        int incl = s[t] + off;
        g_rowptr[1 + i] = incl;
        g_cursor[i] = incl - v;          // exclusive prefix
    }
    if (b == 0 && t == 0) g_rowptr[0] = 0;
}

// ---------------- 3: scatter (+ reset scan statuses) ----------------
__global__ void k_scatter(const int* __restrict__ rows,
                          const int* __restrict__ cols,
                          const float* __restrict__ vals) {
    int e = blockIdx.x * blockDim.x + threadIdx.x;
    if (blockIdx.x == 0 && threadIdx.x < SCAN_NBLK) g_stat[threadIdx.x] = 0;
    if (e < NNZ) {
        int r = rows[e];
        int p = atomicAdd(&g_cursor[r], 1);
        int2 pr;
        pr.x = cols[e];
        pr.y = __float_as_int(vals[e]);
        g_edge[p] = pr;
    }
}

// ---------------- 4: SpMM — warp/node, 2 edges per LDG.128, fp32 ----------------
__global__ void __launch_bounds__(256) k_spmm(int cur) {
    const float* __restrict__ E = cur ? g_E1 : g_E0;
    __shared__ int2 sedge[8][32];
    int warp = (blockIdx.x * blockDim.x + threadIdx.x) >> 5;
    int wid  = threadIdx.x >> 5;
    int lane = threadIdx.x & 31;
    int half = lane >> 4;         // which edge of the pair
    int l16  = lane & 15;         // float4 slot within row (16 x 16B = 256B)
    if (warp >= NN) return;
    int start = g_rowptr[warp];
    int end   = g_rowptr[warp + 1];
    ull a01 = 0, a23 = 0;         // 4 fp32 dims as 2 f32x2
    int e0 = start;
    for (; e0 + 32 <= end; e0 += 32) {
        sedge[wid][lane] = g_edge[e0 + lane];
        __syncwarp();
        #pragma unroll
        for (int p = 0; p < 16; p++) {
            int2 ed = sedge[wid][2 * p + half];
            ull vv = pk2(__int_as_float(ed.y), __int_as_float(ed.y));
            ulonglong2 q = *(const ulonglong2*)&E[ed.x * DD + l16 * 4];
            a01 = fma2(q.x, vv, a01);
            a23 = fma2(q.y, vv, a23);
        }
        __syncwarp();
    }
    int rem = end - e0;
    if (rem > 0) {
        sedge[wid][lane] = (lane < rem) ? g_edge[e0 + lane] : make_int2(0, 0);
        __syncwarp();
        int pairs = (rem + 1) >> 1;
        for (int p = 0; p < pairs; p++) {
            int2 ed = sedge[wid][2 * p + half];
            ull vv = pk2(__int_as_float(ed.y), __int_as_float(ed.y));
            ulonglong2 q = *(const ulonglong2*)&E[ed.x * DD + l16 * 4];
            a01 = fma2(q.x, vv, a01);
            a23 = fma2(q.y, vv, a23);
        }
    }
    // combine the two half-warp edge streams
    float2 f01 = upk(a01), f23 = upk(a23);
    f01.x += __shfl_xor_sync(0xffffffffu, f01.x, 16);
    f01.y += __shfl_xor_sync(0xffffffffu, f01.y, 16);
    f23.x += __shfl_xor_sync(0xffffffffu, f23.x, 16);
    f23.y += __shfl_xor_sync(0xffffffffu, f23.y, 16);
    if (half == 0) {
        float4 r = make_float4(f01.x, f01.y, f23.x, f23.y);
        *(float4*)&g_Lmul[warp * DD + l16 * 4] = r;
    }
}

// ---------------- fused GEMM (FFMA2) + leaky_relu + norm + dual store ----------------
#define TS 132
#define GEMM_SMEM_FLOATS (2 * 64 * TS + 2 * 64 * 64)

__global__ void __launch_bounds__(256, 2) k_gemm(int cur, int l,
                                                 const float* __restrict__ W1,
                                                 const float* __restrict__ b1,
                                                 const float* __restrict__ W2,
                                                 const float* __restrict__ b2) {
    extern __shared__ float smem[];
    float* AsT = smem;                 // [64][132]
    float* RsT = AsT + 64 * TS;        // [64][132]
    float* W1s = RsT + 64 * TS;        // [64][64]
    float* W2s = W1s + 64 * 64;        // [64][64]

    const float* Ecur  = cur ? g_E1 : g_E0;
    float*       Enext = cur ? g_E0 : g_E1;

    int tid  = threadIdx.x;
    int lane = tid & 31;
    int wid  = tid >> 5;
    int tx = tid & 15;
    int ty = tid >> 4;
    int j0 = tx * 4;
    int r0 = ty * 8;
    int n0 = blockIdx.x * 128;
    int lw = l * 64 * 64;
    int lb = l * 64;

    for (int i = tid; i < 4096; i += 256) {
        W1s[i] = W1[lw + i];
        W2s[i] = W2[lw + i];
    }

    const float2* LM2 = (const float2*)g_Lmul;
    const float2* EC2 = (const float2*)Ecur;
    for (int row = wid; row < 128; row += 8) {
        int n = n0 + row;
        float2 lm = make_float2(0.0f, 0.0f), ev = make_float2(0.0f, 0.0f);
        if (n < NN) {
            lm = LM2[n * 32 + lane];
            ev = EC2[n * 32 + lane];
        }
        int k = 2 * lane;
        AsT[k * TS + row]       = lm.x + ev.x;
        AsT[(k + 1) * TS + row] = lm.y + ev.y;
        RsT[k * TS + row]       = lm.x * ev.x;
        RsT[(k + 1) * TS + row] = lm.y * ev.y;
    }
    __syncthreads();

    ull acc[4][4];
    #pragma unroll
    for (int j = 0; j < 4; j++) {
        float b = b1[lb + j0 + j] + b2[lb + j0 + j];
        ull bb = pk2(b, b);
        #pragma unroll
        for (int p = 0; p < 4; p++) acc[p][j] = bb;
    }

    #pragma unroll 4
    for (int k = 0; k < 64; k++) {
        const float* ak = &AsT[k * TS + r0];
        const float* rk = &RsT[k * TS + r0];
        ulonglong2 A01 = *(const ulonglong2*)(ak);
        ulonglong2 A23 = *(const ulonglong2*)(ak + 4);
        ulonglong2 R01 = *(const ulonglong2*)(rk);
        ulonglong2 R23 = *(const ulonglong2*)(rk + 4);
        float4 w1 = *(const float4*)&W1s[k * 64 + j0];
        float4 w2 = *(const float4*)&W2s[k * 64 + j0];
        ull w1d[4] = { pk2(w1.x, w1.x), pk2(w1.y, w1.y), pk2(w1.z, w1.z), pk2(w1.w, w1.w) };
        ull w2d[4] = { pk2(w2.x, w2.x), pk2(w2.y, w2.y), pk2(w2.z, w2.z), pk2(w2.w, w2.w) };
        #pragma unroll
        for (int j = 0; j < 4; j++) {
            acc[0][j] = fma2(A01.x, w1d[j], acc[0][j]);
            acc[0][j] = fma2(R01.x, w2d[j], acc[0][j]);
            acc[1][j] = fma2(A01.y, w1d[j], acc[1][j]);
            acc[1][j] = fma2(R01.y, w2d[j], acc[1][j]);
            acc[2][j] = fma2(A23.x, w1d[j], acc[2][j]);
            acc[2][j] = fma2(R23.x, w2d[j], acc[2][j]);
            acc[3][j] = fma2(A23.y, w1d[j], acc[3][j]);
            acc[3][j] = fma2(R23.y, w2d[j], acc[3][j]);
        }
    }

    float vals_[8][4];
    float sq[8];
    #pragma unroll
    for (int p = 0; p < 4; p++) {
        float sx = 0.0f, sy = 0.0f;
        #pragma unroll
        for (int j = 0; j < 4; j++) {
            float2 v = upk(acc[p][j]);
            v.x = (v.x >= 0.0f) ? v.x : 0.2f * v.x;
            v.y = (v.y >= 0.0f) ? v.y : 0.2f * v.y;
            vals_[2 * p][j]     = v.x;
            vals_[2 * p + 1][j] = v.y;
            sx = fmaf(v.x, v.x, sx);
            sy = fmaf(v.y, v.y, sy);
        }
        sq[2 * p]     = sx;
        sq[2 * p + 1] = sy;
    }
    #pragma unroll
    for (int i = 0; i < 8; i++) {
        #pragma unroll
        for (int off = 1; off <= 8; off <<= 1)
            sq[i] += __shfl_xor_sync(0xffffffffu, sq[i], off);
    }

    int colblk = (l + 1) * 64;
    #pragma unroll
    for (int i = 0; i < 8; i++) {
        int n = n0 + r0 + i;
        if (n < NN) {
            float inv = 1.0f / fmaxf(sqrtf(sq[i]), 1e-12f);
            float4 v = make_float4(vals_[i][0], vals_[i][1], vals_[i][2], vals_[i][3]);
            *(float4*)&Enext[n * DD + j0] = v;
            float4 vn = make_float4(v.x * inv, v.y * inv, v.z * inv, v.w * inv);
            *(float4*)&g_alle[n * 256 + colblk + j0] = vn;
        }
    }
}

// ---------------- final loss ----------------
__global__ void k_loss(const int* __restrict__ users,
                       const int* __restrict__ pos,
                       const int* __restrict__ neg) {
    int warp = (blockIdx.x * blockDim.x + threadIdx.x) >> 5;
    int lane = threadIdx.x & 31;
    if (warp >= NB) return;
    int uu = users[warp];
    int pp = pos[warp];
    int nn = neg[warp];
    const float4* A4 = (const float4*)g_alle;
    float pd = 0, nd = 0, su = 0, sp = 0, sn = 0;
    #pragma unroll
    for (int t = 0; t < 2; t++) {
        float4 u = A4[uu * 64 + lane * 2 + t];
        float4 p = A4[pp * 64 + lane * 2 + t];
        float4 q = A4[nn * 64 + lane * 2 + t];
        pd += u.x * p.x + u.y * p.y + u.z * p.z + u.w * p.w;
        nd += u.x * q.x + u.y * q.y + u.z * q.z + u.w * q.w;
        su += u.x * u.x + u.y * u.y + u.z * u.z + u.w * u.w;
        sp += p.x * p.x + p.y * p.y + p.z * p.z + p.w * p.w;
        sn += q.x * q.x + q.y * q.y + q.z * q.z + q.w * q.w;
    }
    #pragma unroll
    for (int off = 16; off > 0; off >>= 1) {
        pd += __shfl_xor_sync(0xffffffffu, pd, off);
        nd += __shfl_xor_sync(0xffffffffu, nd, off);
        su += __shfl_xor_sync(0xffffffffu, su, off);
        sp += __shfl_xor_sync(0xffffffffu, sp, off);
        sn += __shfl_xor_sync(0xffffffffu, sn, off);
    }
    if (lane == 0) {
        float d = pd - nd;
        float ls = fminf(d, 0.0f) - log1pf(expf(-fabsf(d)));
        atomicAdd(&g_acc[0], ls);
        atomicAdd(&g_acc[1], su);
        atomicAdd(&g_acc[2], sp);
        atomicAdd(&g_acc[3], sn);
    }
}

__global__ void k_finalize(float* out) {
    float bpr = -g_acc[0] / (float)NB;
    float l2norm = (g_acc[1] + g_acc[2] + sqrtf(g_acc[3])) * 0.5f;
    out[0] = bpr + L2_REG * l2norm / (float)NB;
}

// ---------------- launch ----------------
extern "C" void kernel_launch(void* const* d_in, const int* in_sizes, int n_in,
                              void* d_out, int out_size) {
    const int*   users = (const int*)d_in[0];
    const int*   pos   = (const int*)d_in[1];
    const int*   neg   = (const int*)d_in[2];
    const int*   rows  = (const int*)d_in[3];
    const int*   cols  = (const int*)d_in[4];
    const float* vals  = (const float*)d_in[5];
    const float* ue    = (const float*)d_in[6];
    const float* ie    = (const float*)d_in[7];
    const float* W1    = (const float*)d_in[8];
    const float* b1    = (const float*)d_in[9];
    const float* W2    = (const float*)d_in[10];
    const float* b2    = (const float*)d_in[11];
    float* out = (float*)d_out;

    cudaFuncSetAttribute(k_gemm, cudaFuncAttributeMaxDynamicSharedMemorySize,
                         GEMM_SMEM_FLOATS * sizeof(float));

    // 1: count + E init + acc zero
    k_count_init<<<(NNZ + 255) / 256, 256>>>(rows, ue, ie);
    // 2: single-pass scan (builds rowptr + cursor, re-zeroes deg)
    k_scan<<<SCAN_NBLK, SCAN_CHUNK>>>();
    // 3: scatter (resets scan statuses)
    k_scatter<<<(NNZ + 255) / 256, 256>>>(rows, cols, vals);

    // layers (k_spmm layer 0 is launch #4 -> lands in the ncu capture slot)
    int cur = 0;
    for (int l = 0; l < NLAYERS; l++) {
        k_spmm<<<(NN + 7) / 8, 256>>>(cur);
        k_gemm<<<(NN + 127) / 128, 256, GEMM_SMEM_FLOATS * sizeof(float)>>>(
            cur, l, W1, b1, W2, b2);
        cur ^= 1;
    }

    k_loss<<<(NB * 32 + 255) / 256, 256>>>(users, pos, neg);
    k_finalize<<<1, 1>>>(out);
}

// round 6
// speedup vs baseline: 1.0018x; 1.0018x over previous
#include <cuda_runtime.h>
#include <math.h>

// Problem constants
#define NU 50000
#define NI 50000
#define NN 100000          // NU + NI
#define DD 64
#define NNZ 3200000
#define NLAYERS 3
#define NB 4096
#define L2_REG 1e-5f

#define SCAN_CHUNK 1024
#define SCAN_NBLK ((NN + SCAN_CHUNK - 1) / SCAN_CHUNK)   // 98
#define STAT_READY (1 << 30)

// ---------------- device scratch (no allocs allowed) ----------------
__device__ __align__(256) float g_E0[NN * DD];
__device__ __align__(256) float g_E1[NN * DD];
__device__ __align__(256) float g_Lmul[NN * DD];
__device__ __align__(256) float g_alle[NN * DD * (NLAYERS + 1)];   // [N, 256]
__device__ int   g_deg[NN];          // zero-init; re-zeroed by k_scan each call
__device__ int   g_rowptr[NN + 1];
__device__ int   g_cursor[NN];
__device__ __align__(16) int2 g_edge[NNZ];   // (col, val bits)
__device__ int   g_stat[SCAN_NBLK];  // zero-init; reset by k_scatter each call
__device__ float g_acc[4];           // bpr_sum, sum u^2, sum p^2, sum n^2

// ---------------- f32x2 helpers (FFMA2: PTX-only pattern) ----------------
typedef unsigned long long ull;

__device__ __forceinline__ ull fma2(ull a, ull b, ull c) {
    ull d;
    asm("fma.rn.f32x2 %0, %1, %2, %3;" : "=l"(d) : "l"(a), "l"(b), "l"(c));
    return d;
}
__device__ __forceinline__ ull pk2(float lo, float hi) {
    ull d;
    asm("mov.b64 %0, {%1, %2};" : "=l"(d) : "f"(lo), "f"(hi));
    return d;
}
__device__ __forceinline__ float2 upk(ull v) {
    float2 f;
    asm("mov.b64 {%0, %1}, %2;" : "=f"(f.x), "=f"(f.y) : "l"(v));
    return f;
}

// ---------------- 1: count + E init + acc zero ----------------
__global__ void k_count_init(const int* __restrict__ rows,
                             const float* __restrict__ ue,
                             const float* __restrict__ ie) {
    int i = blockIdx.x * blockDim.x + threadIdx.x;
    if (i < NNZ) atomicAdd(&g_deg[rows[i]], 1);
    if (i < NN * (DD / 4)) {
        int n = i >> 4;
        int c = i & 15;
        const float4* src;
        int srow;
        if (n < NU) { src = (const float4*)ue; srow = n; }
        else        { src = (const float4*)ie; srow = n - NU; }
        float4 v = src[srow * 16 + c];
        ((float4*)g_E0)[i] = v;
        ((float4*)g_alle)[n * 64 + c] = v;
    }
    if (i < 4) g_acc[i] = 0.0f;
}

// ---------------- 2: single-pass scan (all 98 blocks co-resident) ----------------
__global__ void k_scan(void) {
    __shared__ int s[SCAN_CHUNK];
    __shared__ int wsum[4];
    __shared__ int s_off;
    int b = blockIdx.x;
    int t = threadIdx.x;
    int i = b * SCAN_CHUNK + t;
    int v = (i < NN) ? g_deg[i] : 0;
    if (i < NN) g_deg[i] = 0;            // maintain zero invariant for next call
    s[t] = v;
    __syncthreads();
    for (int off = 1; off < SCAN_CHUNK; off <<= 1) {
        int x = 0;
        if (t >= off) x = s[t - off];
        __syncthreads();
        s[t] += x;
        __syncthreads();
    }
    if (t == SCAN_CHUNK - 1) atomicExch(&g_stat[b], s[t] | STAT_READY);
    int part = 0;
    if (t < b) {
        int st;
        do { st = atomicAdd(&g_stat[t], 0); } while (!(st & STAT_READY));
        part = st & (STAT_READY - 1);
    }
    #pragma unroll
    for (int off = 16; off > 0; off >>= 1)
        part += __shfl_xor_sync(0xffffffffu, part, off);
    if ((t & 31) == 0 && (t >> 5) < 4) wsum[t >> 5] = part;
    __syncthreads();
    if (t == 0) s_off = wsum[0] + wsum[1] + wsum[2] + wsum[3];
    __syncthreads();
    int off = s_off;
    if (i < NN) {
        int incl = s[t] + off;
        g_rowptr[1 + i] = incl;
        g_cursor[i] = incl - v;
    }
    if (b == 0 && t == 0) g_rowptr[0] = 0;
}

// ---------------- 3: scatter (+ reset scan statuses) ----------------
__global__ void k_scatter(const int* __restrict__ rows,
                          const int* __restrict__ cols,
                          const float* __restrict__ vals) {
    int e = blockIdx.x * blockDim.x + threadIdx.x;
    if (blockIdx.x == 0 && threadIdx.x < SCAN_NBLK) g_stat[threadIdx.x] = 0;
    if (e < NNZ) {
        int r = rows[e];
        int p = atomicAdd(&g_cursor[r], 1);
        int2 pr;
        pr.x = cols[e];
        pr.y = __float_as_int(vals[e]);
        g_edge[p] = pr;
    }
}

// ---------------- 4: SpMM — warp/node, 2 edges per LDG.128, MLP-4 pipeline ----
__global__ void __launch_bounds__(256, 6) k_spmm(int cur) {
    const float* __restrict__ E = cur ? g_E1 : g_E0;
    __shared__ int2 sedge[8][32];
    int warp = (blockIdx.x * blockDim.x + threadIdx.x) >> 5;
    int wid  = threadIdx.x >> 5;
    int lane = threadIdx.x & 31;
    int half = lane >> 4;         // which edge of the pair
    int l16  = lane & 15;         // float4 slot within the 256B row
    if (warp >= NN) return;
    int start = g_rowptr[warp];
    int end   = g_rowptr[warp + 1];
    ull a01 = 0, a23 = 0;
    int e0 = start;
    // full batches: 32 edges, 16 pairs in 4 groups of 4 (4 independent LDG.128/group)
    for (; e0 + 32 <= end; e0 += 32) {
        sedge[wid][lane] = g_edge[e0 + lane];
        __syncwarp();
        #pragma unroll
        for (int p0 = 0; p0 < 16; p0 += 4) {
            int2 eA = sedge[wid][2 * p0 + 0 + half];
            int2 eB = sedge[wid][2 * p0 + 2 + half];
            int2 eC = sedge[wid][2 * p0 + 4 + half];
            int2 eD = sedge[wid][2 * p0 + 6 + half];
            ulonglong2 qA = *(const ulonglong2*)&E[eA.x * DD + l16 * 4];
            ulonglong2 qB = *(const ulonglong2*)&E[eB.x * DD + l16 * 4];
            ulonglong2 qC = *(const ulonglong2*)&E[eC.x * DD + l16 * 4];
            ulonglong2 qD = *(const ulonglong2*)&E[eD.x * DD + l16 * 4];
            ull vA = pk2(__int_as_float(eA.y), __int_as_float(eA.y));
            ull vB = pk2(__int_as_float(eB.y), __int_as_float(eB.y));
            ull vC = pk2(__int_as_float(eC.y), __int_as_float(eC.y));
            ull vD = pk2(__int_as_float(eD.y), __int_as_float(eD.y));
            a01 = fma2(qA.x, vA, a01); a23 = fma2(qA.y, vA, a23);
            a01 = fma2(qB.x, vB, a01); a23 = fma2(qB.y, vB, a23);
            a01 = fma2(qC.x, vC, a01); a23 = fma2(qC.y, vC, a23);
            a01 = fma2(qD.x, vD, a01); a23 = fma2(qD.y, vD, a23);
        }
        __syncwarp();
    }
    int rem = end - e0;
    if (rem > 0) {
        // zero-pad so grouped loop needs no predication (col 0 * val 0 is harmless)
        sedge[wid][lane] = (lane < rem) ? g_edge[e0 + lane] : make_int2(0, 0);
        __syncwarp();
        int npairs = (((rem + 1) >> 1) + 3) & ~3;   // multiple of 4, <= 16
        for (int p0 = 0; p0 < npairs; p0 += 4) {
            int2 eA = sedge[wid][2 * p0 + 0 + half];
            int2 eB = sedge[wid][2 * p0 + 2 + half];
            int2 eC = sedge[wid][2 * p0 + 4 + half];
            int2 eD = sedge[wid][2 * p0 + 6 + half];
            ulonglong2 qA = *(const ulonglong2*)&E[eA.x * DD + l16 * 4];
            ulonglong2 qB = *(const ulonglong2*)&E[eB.x * DD + l16 * 4];
            ulonglong2 qC = *(const ulonglong2*)&E[eC.x * DD + l16 * 4];
            ulonglong2 qD = *(const ulonglong2*)&E[eD.x * DD + l16 * 4];
            ull vA = pk2(__int_as_float(eA.y), __int_as_float(eA.y));
            ull vB = pk2(__int_as_float(eB.y), __int_as_float(eB.y));
            ull vC = pk2(__int_as_float(eC.y), __int_as_float(eC.y));
            ull vD = pk2(__int_as_float(eD.y), __int_as_float(eD.y));
            a01 = fma2(qA.x, vA, a01); a23 = fma2(qA.y, vA, a23);
            a01 = fma2(qB.x, vB, a01); a23 = fma2(qB.y, vB, a23);
            a01 = fma2(qC.x, vC, a01); a23 = fma2(qC.y, vC, a23);
            a01 = fma2(qD.x, vD, a01); a23 = fma2(qD.y, vD, a23);
        }
    }
    // combine the two half-warp edge streams
    float2 f01 = upk(a01), f23 = upk(a23);
    f01.x += __shfl_xor_sync(0xffffffffu, f01.x, 16);
    f01.y += __shfl_xor_sync(0xffffffffu, f01.y, 16);
    f23.x += __shfl_xor_sync(0xffffffffu, f23.x, 16);
    f23.y += __shfl_xor_sync(0xffffffffu, f23.y, 16);
    if (half == 0) {
        float4 r = make_float4(f01.x, f01.y, f23.x, f23.y);
        *(float4*)&g_Lmul[warp * DD + l16 * 4] = r;
    }
}

// ---------------- fused GEMM (FFMA2) + leaky_relu + norm + dual store ----------------
#define TS 132
#define GEMM_SMEM_FLOATS (2 * 64 * TS + 2 * 64 * 64)

__global__ void __launch_bounds__(256, 2) k_gemm(int cur, int l,
                                                 const float* __restrict__ W1,
                                                 const float* __restrict__ b1,
                                                 const float* __restrict__ W2,
                                                 const float* __restrict__ b2) {
    extern __shared__ float smem[];
    float* AsT = smem;                 // [64][132]
    float* RsT = AsT + 64 * TS;        // [64][132]
    float* W1s = RsT + 64 * TS;        // [64][64]
    float* W2s = W1s + 64 * 64;        // [64][64]

    const float* Ecur  = cur ? g_E1 : g_E0;
    float*       Enext = cur ? g_E0 : g_E1;

    int tid  = threadIdx.x;
    int lane = tid & 31;
    int wid  = tid >> 5;
    int tx = tid & 15;
    int ty = tid >> 4;
    int j0 = tx * 4;
    int r0 = ty * 8;
    int n0 = blockIdx.x * 128;
    int lw = l * 64 * 64;
    int lb = l * 64;

    for (int i = tid; i < 4096; i += 256) {
        W1s[i] = W1[lw + i];
        W2s[i] = W2[lw + i];
    }

    // staging: warp per row; lane covers k = lane and k = lane+32
    // (STS address step between lanes = TS floats -> 4 banks apart: 4-way conflict,
    //  vs 8-way with the old k=2*lane layout)
    for (int row = wid; row < 128; row += 8) {
        int n = n0 + row;
        float lmA = 0.0f, lmB = 0.0f, evA = 0.0f, evB = 0.0f;
        if (n < NN) {
            lmA = g_Lmul[n * DD + lane];
            lmB = g_Lmul[n * DD + lane + 32];
            evA = Ecur[n * DD + lane];
            evB = Ecur[n * DD + lane + 32];
        }
        AsT[lane * TS + row]        = lmA + evA;
        AsT[(lane + 32) * TS + row] = lmB + evB;
        RsT[lane * TS + row]        = lmA * evA;
        RsT[(lane + 32) * TS + row] = lmB * evB;
    }
    __syncthreads();

    ull acc[4][4];
    #pragma unroll
    for (int j = 0; j < 4; j++) {
        float b = b1[lb + j0 + j] + b2[lb + j0 + j];
        ull bb = pk2(b, b);
        #pragma unroll
        for (int p = 0; p < 4; p++) acc[p][j] = bb;
    }

    #pragma unroll 4
    for (int k = 0; k < 64; k++) {
        const float* ak = &AsT[k * TS + r0];
        const float* rk = &RsT[k * TS + r0];
        ulonglong2 A01 = *(const ulonglong2*)(ak);
        ulonglong2 A23 = *(const ulonglong2*)(ak + 4);
        ulonglong2 R01 = *(const ulonglong2*)(rk);
        ulonglong2 R23 = *(const ulonglong2*)(rk + 4);
        float4 w1 = *(const float4*)&W1s[k * 64 + j0];
        float4 w2 = *(const float4*)&W2s[k * 64 + j0];
        ull w1d[4] = { pk2(w1.x, w1.x), pk2(w1.y, w1.y), pk2(w1.z, w1.z), pk2(w1.w, w1.w) };
        ull w2d[4] = { pk2(w2.x, w2.x), pk2(w2.y, w2.y), pk2(w2.z, w2.z), pk2(w2.w, w2.w) };
        #pragma unroll
        for (int j = 0; j < 4; j++) {
            acc[0][j] = fma2(A01.x, w1d[j], acc[0][j]);
            acc[0][j] = fma2(R01.x, w2d[j], acc[0][j]);
            acc[1][j] = fma2(A01.y, w1d[j], acc[1][j]);
            acc[1][j] = fma2(R01.y, w2d[j], acc[1][j]);
            acc[2][j] = fma2(A23.x, w1d[j], acc[2][j]);
            acc[2][j] = fma2(R23.x, w2d[j], acc[2][j]);
            acc[3][j] = fma2(A23.y, w1d[j], acc[3][j]);
            acc[3][j] = fma2(R23.y, w2d[j], acc[3][j]);
        }
    }

    float vals_[8][4];
    float sq[8];
    #pragma unroll
    for (int p = 0; p < 4; p++) {
        float sx = 0.0f, sy = 0.0f;
        #pragma unroll
        for (int j = 0; j < 4; j++) {
            float2 v = upk(acc[p][j]);
            v.x = (v.x >= 0.0f) ? v.x : 0.2f * v.x;
            v.y = (v.y >= 0.0f) ? v.y : 0.2f * v.y;
            vals_[2 * p][j]     = v.x;
            vals_[2 * p + 1][j] = v.y;
            sx = fmaf(v.x, v.x, sx);
            sy = fmaf(v.y, v.y, sy);
        }
        sq[2 * p]     = sx;
        sq[2 * p + 1] = sy;
    }
    #pragma unroll
    for (int i = 0; i < 8; i++) {
        #pragma unroll
        for (int off = 1; off <= 8; off <<= 1)
            sq[i] += __shfl_xor_sync(0xffffffffu, sq[i], off);
    }

    int colblk = (l + 1) * 64;
    #pragma unroll
    for (int i = 0; i < 8; i++) {
        int n = n0 + r0 + i;
        if (n < NN) {
            float inv = 1.0f / fmaxf(sqrtf(sq[i]), 1e-12f);
            float4 v = make_float4(vals_[i][0], vals_[i][1], vals_[i][2], vals_[i][3]);
            *(float4*)&Enext[n * DD + j0] = v;
            float4 vn = make_float4(v.x * inv, v.y * inv, v.z * inv, v.w * inv);
            *(float4*)&g_alle[n * 256 + colblk + j0] = vn;
        }
    }
}

// ---------------- final loss ----------------
__global__ void k_loss(const int* __restrict__ users,
                       const int* __restrict__ pos,
                       const int* __restrict__ neg) {
    int warp = (blockIdx.x * blockDim.x + threadIdx.x) >> 5;
    int lane = threadIdx.x & 31;
    if (warp >= NB) return;
    int uu = users[warp];
    int pp = pos[warp];
    int nn = neg[warp];
    const float4* A4 = (const float4*)g_alle;
    float pd = 0, nd = 0, su = 0, sp = 0, sn = 0;
    #pragma unroll
    for (int t = 0; t < 2; t++) {
        float4 u = A4[uu * 64 + lane * 2 + t];
        float4 p = A4[pp * 64 + lane * 2 + t];
        float4 q = A4[nn * 64 + lane * 2 + t];
        pd += u.x * p.x + u.y * p.y + u.z * p.z + u.w * p.w;
        nd += u.x * q.x + u.y * q.y + u.z * q.z + u.w * q.w;
        su += u.x * u.x + u.y * u.y + u.z * u.z + u.w * u.w;
        sp += p.x * p.x + p.y * p.y + p.z * p.z + p.w * p.w;
        sn += q.x * q.x + q.y * q.y + q.z * q.z + q.w * q.w;
    }
    #pragma unroll
    for (int off = 16; off > 0; off >>= 1) {
        pd += __shfl_xor_sync(0xffffffffu, pd, off);
        nd += __shfl_xor_sync(0xffffffffu, nd, off);
        su += __shfl_xor_sync(0xffffffffu, su, off);
        sp += __shfl_xor_sync(0xffffffffu, sp, off);
        sn += __shfl_xor_sync(0xffffffffu, sn, off);
    }
    if (lane == 0) {
        float d = pd - nd;
        float ls = fminf(d, 0.0f) - log1pf(expf(-fabsf(d)));
        atomicAdd(&g_acc[0], ls);
        atomicAdd(&g_acc[1], su);
        atomicAdd(&g_acc[2], sp);
        atomicAdd(&g_acc[3], sn);
    }
}

__global__ void k_finalize(float* out) {
    float bpr = -g_acc[0] / (float)NB;
    float l2norm = (g_acc[1] + g_acc[2] + sqrtf(g_acc[3])) * 0.5f;
    out[0] = bpr + L2_REG * l2norm / (float)NB;
}

// ---------------- launch ----------------
extern "C" void kernel_launch(void* const* d_in, const int* in_sizes, int n_in,
                              void* d_out, int out_size) {
    const int*   users = (const int*)d_in[0];
    const int*   pos   = (const int*)d_in[1];
    const int*   neg   = (const int*)d_in[2];
    const int*   rows  = (const int*)d_in[3];
    const int*   cols  = (const int*)d_in[4];
    const float* vals  = (const float*)d_in[5];
    const float* ue    = (const float*)d_in[6];
    const float* ie    = (const float*)d_in[7];
    const float* W1    = (const float*)d_in[8];
    const float* b1    = (const float*)d_in[9];
    const float* W2    = (const float*)d_in[10];
    const float* b2    = (const float*)d_in[11];
    float* out = (float*)d_out;

    cudaFuncSetAttribute(k_gemm, cudaFuncAttributeMaxDynamicSharedMemorySize,
                         GEMM_SMEM_FLOATS * sizeof(float));

    // 1: count + E init + acc zero
    k_count_init<<<(NNZ + 255) / 256, 256>>>(rows, ue, ie);
    // 2: single-pass scan (builds rowptr + cursor, re-zeroes deg)
    k_scan<<<SCAN_NBLK, SCAN_CHUNK>>>();
    // 3: scatter (resets scan statuses)
    k_scatter<<<(NNZ + 255) / 256, 256>>>(rows, cols, vals);

    // layers (k_spmm layer 0 is launch #4 -> ncu capture slot)
    int cur = 0;
    for (int l = 0; l < NLAYERS; l++) {
        k_spmm<<<(NN + 7) / 8, 256>>>(cur);
        k_gemm<<<(NN + 127) / 128, 256, GEMM_SMEM_FLOATS * sizeof(float)>>>(
            cur, l, W1, b1, W2, b2);
        cur ^= 1;
    }

    k_loss<<<(NB * 32 + 255) / 256, 256>>>(users, pos, neg);
    k_finalize<<<1, 1>>>(out);
}

// round 7
// speedup vs baseline: 1.0297x; 1.0278x over previous
#include <cuda_runtime.h>
#include <math.h>

// Problem constants
#define NU 50000
#define NI 50000
#define NN 100000          // NU + NI
#define DD 64
#define NNZ 3200000
#define NLAYERS 3
#define NB 4096
#define L2_REG 1e-5f

#define SCAN_CHUNK 1024
#define SCAN_NBLK ((NN + SCAN_CHUNK - 1) / SCAN_CHUNK)   // 98
#define STAT_READY (1 << 30)
#define LOSS_NBLK (NB / 8)                               // 512 blocks of 8 warps

// ---------------- device scratch (no allocs allowed) ----------------
__device__ __align__(256) float g_E0[NN * DD];
__device__ __align__(256) float g_E1[NN * DD];
__device__ __align__(256) unsigned int g_B0[NN * 32];   // bf16x2 shadow of E0
__device__ __align__(256) unsigned int g_B1[NN * 32];   // bf16x2 shadow of E1
__device__ __align__(256) float g_Lmul[NN * DD];
__device__ __align__(256) float g_alle[NN * DD * (NLAYERS + 1)];   // [N, 256]
__device__ int   g_deg[NN];          // zero-init; re-zeroed by scan each call
__device__ int   g_rowptr[NN + 1];
__device__ int   g_cursor[NN];
__device__ __align__(16) int2 g_edge[NNZ];   // (col, val bits)
__device__ int   g_stat[SCAN_NBLK];  // zero-init; reset in-kernel each call
__device__ int   g_bar;              // scan->scatter barrier (self-resetting)
__device__ int   g_bar2;
__device__ int   g_done;             // loss finalize counter (self-resetting)
__device__ float g_acc[4];           // bpr_sum, u^2, p^2, n^2 (finalize resets)

// ---------------- f32x2 helpers (FFMA2: PTX-only pattern) ----------------
typedef unsigned long long ull;

__device__ __forceinline__ ull fma2(ull a, ull b, ull c) {
    ull d;
    asm("fma.rn.f32x2 %0, %1, %2, %3;" : "=l"(d) : "l"(a), "l"(b), "l"(c));
    return d;
}
__device__ __forceinline__ ull pk2(float lo, float hi) {
    ull d;
    asm("mov.b64 %0, {%1, %2};" : "=l"(d) : "f"(lo), "f"(hi));
    return d;
}
__device__ __forceinline__ float2 upk(ull v) {
    float2 f;
    asm("mov.b64 {%0, %1}, %2;" : "=f"(f.x), "=f"(f.y) : "l"(v));
    return f;
}
__device__ __forceinline__ unsigned int bf2pack(float lo, float hi) {
    unsigned int r;
    asm("cvt.rn.bf16x2.f32 %0, %1, %2;" : "=r"(r) : "f"(hi), "f"(lo));
    return r;
}
// acc += bf16x2 widened to f32x2, times vv (both halves = edge weight)
__device__ __forceinline__ void bfma(ull& acc, unsigned int bits, ull vv) {
    unsigned int lo = bits << 16;
    unsigned int hi = bits & 0xffff0000u;
    ull pair;
    asm("mov.b64 %0, {%1, %2};" : "=l"(pair) : "r"(lo), "r"(hi));
    acc = fma2(pair, vv, acc);
}

// ---------------- 1: count + E init (fp32 + bf16 shadow) ----------------
__global__ void k_count_init(const int* __restrict__ rows,
                             const float* __restrict__ ue,
                             const float* __restrict__ ie) {
    int i = blockIdx.x * blockDim.x + threadIdx.x;
    if (i < NNZ) atomicAdd(&g_deg[rows[i]], 1);
    if (i < NN * (DD / 4)) {
        int n = i >> 4;
        int c = i & 15;
        const float4* src;
        int srow;
        if (n < NU) { src = (const float4*)ue; srow = n; }
        else        { src = (const float4*)ie; srow = n - NU; }
        float4 v = src[srow * 16 + c];
        ((float4*)g_E0)[i] = v;
        ((float4*)g_alle)[n * 64 + c] = v;
        uint2 b;
        b.x = bf2pack(v.x, v.y);
        b.y = bf2pack(v.z, v.w);
        ((uint2*)g_B0)[i] = b;
    }
}

// ---------------- 2: fused scan + scatter (98 co-resident blocks) ----------------
__global__ void k_scan_scatter(const int* __restrict__ rows,
                               const int* __restrict__ cols,
                               const float* __restrict__ vals) {
    __shared__ int s[SCAN_CHUNK];
    __shared__ int wsum[4];
    __shared__ int s_off;
    int b = blockIdx.x;
    int t = threadIdx.x;
    int i = b * SCAN_CHUNK + t;
    int v = (i < NN) ? g_deg[i] : 0;
    if (i < NN) g_deg[i] = 0;            // maintain zero invariant
    s[t] = v;
    __syncthreads();
    for (int off = 1; off < SCAN_CHUNK; off <<= 1) {
        int x = 0;
        if (t >= off) x = s[t - off];
        __syncthreads();
        s[t] += x;
        __syncthreads();
    }
    if (t == SCAN_CHUNK - 1) atomicExch(&g_stat[b], s[t] | STAT_READY);
    int part = 0;
    if (t < b) {
        int st;
        do { st = atomicAdd(&g_stat[t], 0); } while (!(st & STAT_READY));
        part = st & (STAT_READY - 1);
    }
    #pragma unroll
    for (int off = 16; off > 0; off >>= 1)
        part += __shfl_xor_sync(0xffffffffu, part, off);
    if ((t & 31) == 0 && (t >> 5) < 4) wsum[t >> 5] = part;
    __syncthreads();
    if (t == 0) s_off = wsum[0] + wsum[1] + wsum[2] + wsum[3];
    __syncthreads();
    int off = s_off;
    if (i < NN) {
        int incl = s[t] + off;
        g_rowptr[1 + i] = incl;
        g_cursor[i] = incl - v;
    }
    if (b == 0 && t == 0) g_rowptr[0] = 0;

    // ---- grid barrier (all 98 blocks co-resident) ----
    __threadfence();
    __syncthreads();
    if (t == 0) {
        atomicAdd(&g_bar, 1);
        while (atomicAdd(&g_bar, 0) < SCAN_NBLK) { }
        g_stat[b] = 0;                          // safe: all lookbacks done
        int r2 = atomicAdd(&g_bar2, 1);
        if (r2 == SCAN_NBLK - 1) { g_bar = 0; g_bar2 = 0; }   // last resets
    }
    __syncthreads();

    // ---- scatter: grid-stride over edges ----
    for (int e = b * SCAN_CHUNK + t; e < NNZ; e += SCAN_NBLK * SCAN_CHUNK) {
        int r = rows[e];
        int p = atomicAdd(&g_cursor[r], 1);
        int2 pr;
        pr.x = cols[e];
        pr.y = __float_as_int(vals[e]);
        g_edge[p] = pr;
    }
}

// ---------------- 3: SpMM — warp/node, bf16 rows, 4 edges per LDG.128 ----------
__global__ void __launch_bounds__(256) k_spmm(int cur) {
    const uint4* __restrict__ B4 = (const uint4*)(cur ? g_B1 : g_B0);
    __shared__ int2 sedge[8][32];
    int warp = (blockIdx.x * blockDim.x + threadIdx.x) >> 5;
    int wid  = threadIdx.x >> 5;
    int lane = threadIdx.x & 31;
    int g    = lane >> 3;         // edge slot within group of 4
    int sub  = lane & 7;          // uint4 slot within the 128B bf16 row
    if (warp >= NN) return;
    int start = g_rowptr[warp];
    int end   = g_rowptr[warp + 1];
    ull a0 = 0, a1 = 0, a2 = 0, a3 = 0;   // dims sub*8 + {0,1},{2,3},{4,5},{6,7}
    int e0 = start;
    for (; e0 + 32 <= end; e0 += 32) {
        sedge[wid][lane] = g_edge[e0 + lane];
        __syncwarp();
        #pragma unroll
        for (int i0 = 0; i0 < 8; i0 += 4) {
            int2 eA = sedge[wid][4 * (i0 + 0) + g];
            int2 eB = sedge[wid][4 * (i0 + 1) + g];
            int2 eC = sedge[wid][4 * (i0 + 2) + g];
            int2 eD = sedge[wid][4 * (i0 + 3) + g];
            uint4 qA = B4[eA.x * 8 + sub];
            uint4 qB = B4[eB.x * 8 + sub];
            uint4 qC = B4[eC.x * 8 + sub];
            uint4 qD = B4[eD.x * 8 + sub];
            ull vA = pk2(__int_as_float(eA.y), __int_as_float(eA.y));
            ull vB = pk2(__int_as_float(eB.y), __int_as_float(eB.y));
            ull vC = pk2(__int_as_float(eC.y), __int_as_float(eC.y));
            ull vD = pk2(__int_as_float(eD.y), __int_as_float(eD.y));
            bfma(a0, qA.x, vA); bfma(a1, qA.y, vA); bfma(a2, qA.z, vA); bfma(a3, qA.w, vA);
            bfma(a0, qB.x, vB); bfma(a1, qB.y, vB); bfma(a2, qB.z, vB); bfma(a3, qB.w, vB);
            bfma(a0, qC.x, vC); bfma(a1, qC.y, vC); bfma(a2, qC.z, vC); bfma(a3, qC.w, vC);
            bfma(a0, qD.x, vD); bfma(a1, qD.y, vD); bfma(a2, qD.z, vD); bfma(a3, qD.w, vD);
        }
        __syncwarp();
    }
    int rem = end - e0;
    if (rem > 0) {
        sedge[wid][lane] = (lane < rem) ? g_edge[e0 + lane] : make_int2(0, 0);
        __syncwarp();
        int ngrp = (rem + 3) >> 2;
        for (int i = 0; i < ngrp; i++) {
            int2 ed = sedge[wid][4 * i + g];
            uint4 q = B4[ed.x * 8 + sub];
            ull vv = pk2(__int_as_float(ed.y), __int_as_float(ed.y));
            bfma(a0, q.x, vv); bfma(a1, q.y, vv); bfma(a2, q.z, vv); bfma(a3, q.w, vv);
        }
    }
    // reduce across the 4 edge-groups (lane bits 3,4)
    float2 f0 = upk(a0), f1 = upk(a1), f2 = upk(a2), f3 = upk(a3);
    #pragma unroll
    for (int off = 8; off <= 16; off <<= 1) {
        f0.x += __shfl_xor_sync(0xffffffffu, f0.x, off);
        f0.y += __shfl_xor_sync(0xffffffffu, f0.y, off);
        f1.x += __shfl_xor_sync(0xffffffffu, f1.x, off);
        f1.y += __shfl_xor_sync(0xffffffffu, f1.y, off);
        f2.x += __shfl_xor_sync(0xffffffffu, f2.x, off);
        f2.y += __shfl_xor_sync(0xffffffffu, f2.y, off);
        f3.x += __shfl_xor_sync(0xffffffffu, f3.x, off);
        f3.y += __shfl_xor_sync(0xffffffffu, f3.y, off);
    }
    if (lane < 8) {
        *(float4*)&g_Lmul[warp * DD + lane * 8]     = make_float4(f0.x, f0.y, f1.x, f1.y);
        *(float4*)&g_Lmul[warp * DD + lane * 8 + 4] = make_float4(f2.x, f2.y, f3.x, f3.y);
    }
}

// ---------------- 4: fused GEMM (FFMA2) + leaky_relu + norm + dual store --------
#define TS 132
#define GEMM_SMEM_FLOATS (2 * 64 * TS + 2 * 64 * 64)

__global__ void __launch_bounds__(256, 2) k_gemm(int cur, int l,
                                                 const float* __restrict__ W1,
                                                 const float* __restrict__ b1,
                                                 const float* __restrict__ W2,
                                                 const float* __restrict__ b2) {
    extern __shared__ float smem[];
    float* AsT = smem;                 // [64][132]
    float* RsT = AsT + 64 * TS;        // [64][132]
    float* W1s = RsT + 64 * TS;        // [64][64]
    float* W2s = W1s + 64 * 64;        // [64][64]

    const float*  Ecur  = cur ? g_E1 : g_E0;
    float*        Enext = cur ? g_E0 : g_E1;
    unsigned int* Bnext = cur ? g_B0 : g_B1;

    int tid  = threadIdx.x;
    int lane = tid & 31;
    int wid  = tid >> 5;
    int tx = tid & 15;
    int ty = tid >> 4;
    int j0 = tx * 4;
    int r0 = ty * 8;
    int n0 = blockIdx.x * 128;
    int lw = l * 64 * 64;
    int lb = l * 64;

    for (int i = tid; i < 4096; i += 256) {
        W1s[i] = W1[lw + i];
        W2s[i] = W2[lw + i];
    }

    for (int row = wid; row < 128; row += 8) {
        int n = n0 + row;
        float lmA = 0.0f, lmB = 0.0f, evA = 0.0f, evB = 0.0f;
        if (n < NN) {
            lmA = g_Lmul[n * DD + lane];
            lmB = g_Lmul[n * DD + lane + 32];
            evA = Ecur[n * DD + lane];
            evB = Ecur[n * DD + lane + 32];
        }
        AsT[lane * TS + row]        = lmA + evA;
        AsT[(lane + 32) * TS + row] = lmB + evB;
        RsT[lane * TS + row]        = lmA * evA;
        RsT[(lane + 32) * TS + row] = lmB * evB;
    }
    __syncthreads();

    ull acc[4][4];
    #pragma unroll
    for (int j = 0; j < 4; j++) {
        float b = b1[lb + j0 + j] + b2[lb + j0 + j];
        ull bb = pk2(b, b);
        #pragma unroll
        for (int p = 0; p < 4; p++) acc[p][j] = bb;
    }

    #pragma unroll 4
    for (int k = 0; k < 64; k++) {
        const float* ak = &AsT[k * TS + r0];
        const float* rk = &RsT[k * TS + r0];
        ulonglong2 A01 = *(const ulonglong2*)(ak);
        ulonglong2 A23 = *(const ulonglong2*)(ak + 4);
        ulonglong2 R01 = *(const ulonglong2*)(rk);
        ulonglong2 R23 = *(const ulonglong2*)(rk + 4);
        float4 w1 = *(const float4*)&W1s[k * 64 + j0];
        float4 w2 = *(const float4*)&W2s[k * 64 + j0];
        ull w1d[4] = { pk2(w1.x, w1.x), pk2(w1.y, w1.y), pk2(w1.z, w1.z), pk2(w1.w, w1.w) };
        ull w2d[4] = { pk2(w2.x, w2.x), pk2(w2.y, w2.y), pk2(w2.z, w2.z), pk2(w2.w, w2.w) };
        #pragma unroll
        for (int j = 0; j < 4; j++) {
            acc[0][j] = fma2(A01.x, w1d[j], acc[0][j]);
            acc[0][j] = fma2(R01.x, w2d[j], acc[0][j]);
            acc[1][j] = fma2(A01.y, w1d[j], acc[1][j]);
            acc[1][j] = fma2(R01.y, w2d[j], acc[1][j]);
            acc[2][j] = fma2(A23.x, w1d[j], acc[2][j]);
            acc[2][j] = fma2(R23.x, w2d[j], acc[2][j]);
            acc[3][j] = fma2(A23.y, w1d[j], acc[3][j]);
            acc[3][j] = fma2(R23.y, w2d[j], acc[3][j]);
        }
    }

    float vals_[8][4];
    float sq[8];
    #pragma unroll
    for (int p = 0; p < 4; p++) {
        float sx = 0.0f, sy = 0.0f;
        #pragma unroll
        for (int j = 0; j < 4; j++) {
            float2 v = upk(acc[p][j]);
            v.x = (v.x >= 0.0f) ? v.x : 0.2f * v.x;
            v.y = (v.y >= 0.0f) ? v.y : 0.2f * v.y;
            vals_[2 * p][j]     = v.x;
            vals_[2 * p + 1][j] = v.y;
            sx = fmaf(v.x, v.x, sx);
            sy = fmaf(v.y, v.y, sy);
        }
        sq[2 * p]     = sx;
        sq[2 * p + 1] = sy;
    }
    #pragma unroll
    for (int i = 0; i < 8; i++) {
        #pragma unroll
        for (int off = 1; off <= 8; off <<= 1)
            sq[i] += __shfl_xor_sync(0xffffffffu, sq[i], off);
    }

    int colblk = (l + 1) * 64;
    #pragma unroll
    for (int i = 0; i < 8; i++) {
        int n = n0 + r0 + i;
        if (n < NN) {
            float inv = 1.0f / fmaxf(sqrtf(sq[i]), 1e-12f);
            float4 v = make_float4(vals_[i][0], vals_[i][1], vals_[i][2], vals_[i][3]);
            *(float4*)&Enext[n * DD + j0] = v;
            uint2 bv;
            bv.x = bf2pack(v.x, v.y);
            bv.y = bf2pack(v.z, v.w);
            *(uint2*)&Bnext[n * 32 + j0 / 2] = bv;
            float4 vn = make_float4(v.x * inv, v.y * inv, v.z * inv, v.w * inv);
            *(float4*)&g_alle[n * 256 + colblk + j0] = vn;
        }
    }
}

// ---------------- 5: loss + fused finalize ----------------
__global__ void k_loss(const int* __restrict__ users,
                       const int* __restrict__ pos,
                       const int* __restrict__ neg,
                       float* __restrict__ out) {
    int warp = (blockIdx.x * blockDim.x + threadIdx.x) >> 5;
    int lane = threadIdx.x & 31;
    if (warp < NB) {
        int uu = users[warp];
        int pp = pos[warp];
        int nn = neg[warp];
        const float4* A4 = (const float4*)g_alle;
        float pd = 0, nd = 0, su = 0, sp = 0, sn = 0;
        #pragma unroll
        for (int t = 0; t < 2; t++) {
            float4 u = A4[uu * 64 + lane * 2 + t];
            float4 p = A4[pp * 64 + lane * 2 + t];
            float4 q = A4[nn * 64 + lane * 2 + t];
            pd += u.x * p.x + u.y * p.y + u.z * p.z + u.w * p.w;
            nd += u.x * q.x + u.y * q.y + u.z * q.z + u.w * q.w;
            su += u.x * u.x + u.y * u.y + u.z * u.z + u.w * u.w;
            sp += p.x * p.x + p.y * p.y + p.z * p.z + p.w * p.w;
            sn += q.x * q.x + q.y * q.y + q.z * q.z + q.w * q.w;
        }
        #pragma unroll
        for (int off = 16; off > 0; off >>= 1) {
            pd += __shfl_xor_sync(0xffffffffu, pd, off);
            nd += __shfl_xor_sync(0xffffffffu, nd, off);
            su += __shfl_xor_sync(0xffffffffu, su, off);
            sp += __shfl_xor_sync(0xffffffffu, sp, off);
            sn += __shfl_xor_sync(0xffffffffu, sn, off);
        }
        if (lane == 0) {
            float d = pd - nd;
            float ls = fminf(d, 0.0f) - log1pf(expf(-fabsf(d)));
            atomicAdd(&g_acc[0], ls);
            atomicAdd(&g_acc[1], su);
            atomicAdd(&g_acc[2], sp);
            atomicAdd(&g_acc[3], sn);
        }
    }
    // last-block finalize
    __threadfence();
    __syncthreads();
    if (threadIdx.x == 0) {
        int r = atomicAdd(&g_done, 1);
        if (r == LOSS_NBLK - 1) {
            float a0 = atomicAdd(&g_acc[0], 0.0f);
            float a1 = atomicAdd(&g_acc[1], 0.0f);
            float a2 = atomicAdd(&g_acc[2], 0.0f);
            float a3 = atomicAdd(&g_acc[3], 0.0f);
            float bpr = -a0 / (float)NB;
            float l2norm = (a1 + a2 + sqrtf(a3)) * 0.5f;
            out[0] = bpr + L2_REG * l2norm / (float)NB;
            g_acc[0] = 0.0f; g_acc[1] = 0.0f; g_acc[2] = 0.0f; g_acc[3] = 0.0f;
            g_done = 0;
        }
    }
}

// ---------------- launch ----------------
extern "C" void kernel_launch(void* const* d_in, const int* in_sizes, int n_in,
                              void* d_out, int out_size) {
    const int*   users = (const int*)d_in[0];
    const int*   pos   = (const int*)d_in[1];
    const int*   neg   = (const int*)d_in[2];
    const int*   rows  = (const int*)d_in[3];
    const int*   cols  = (const int*)d_in[4];
    const float* vals  = (const float*)d_in[5];
    const float* ue    = (const float*)d_in[6];
    const float* ie    = (const float*)d_in[7];
    const float* W1    = (const float*)d_in[8];
    const float* b1    = (const float*)d_in[9];
    const float* W2    = (const float*)d_in[10];
    const float* b2    = (const float*)d_in[11];
    float* out = (float*)d_out;

    cudaFuncSetAttribute(k_gemm, cudaFuncAttributeMaxDynamicSharedMemorySize,
                         GEMM_SMEM_FLOATS * sizeof(float));

    // 1: count + E init (fp32 + bf16 shadow)
    k_count_init<<<(NNZ + 255) / 256, 256>>>(rows, ue, ie);
    // 2: fused scan + scatter (in-kernel grid barrier)
    k_scan_scatter<<<SCAN_NBLK, SCAN_CHUNK>>>(rows, cols, vals);

    // layers (launch #4 = k_gemm L0 -> ncu capture slot)
    int cur = 0;
    for (int l = 0; l < NLAYERS; l++) {
        k_spmm<<<(NN + 7) / 8, 256>>>(cur);
        k_gemm<<<(NN + 127) / 128, 256, GEMM_SMEM_FLOATS * sizeof(float)>>>(
            cur, l, W1, b1, W2, b2);
        cur ^= 1;
    }

    // loss + fused finalize
    k_loss<<<LOSS_NBLK, 256>>>(users, pos, neg, out);
}